// round 15
// baseline (speedup 1.0000x reference)
#include <cuda_runtime.h>
#include <cuda_fp16.h>
#include <cuda_bf16.h>
#include <math.h>

#define NODES 100000
#define EMAX  3200000
#define DIMM  256

// ---------------- scratch (device globals; no allocation allowed) ----------------
// Packed bf16 pairs: word = bf16(k even) | bf16(k odd)<<16, layout [row][K/2]
__device__ unsigned g_a0h[(size_t)NODES * 128];
__device__ unsigned g_a0l[(size_t)NODES * 128];
__device__ unsigned g_zh [(size_t)NODES * 128];
__device__ unsigned g_zl [(size_t)NODES * 128];
__device__ float  g_h[(size_t)NODES * DIMM];      // fp32 hidden (layer 3 only, for fc)
__device__ __half g_hhalf[(size_t)NODES * DIMM];  // raw-h fp16 gather table
__device__ float g_bns1[DIMM], g_bnq1[DIMM];      // zero-invariant (cleanup kernel)
__device__ float g_bns2[DIMM], g_bnq2[DIMM];
__device__ float g_sc1[DIMM], g_sh1[DIMM];        // BN affine coefs
__device__ float g_sc2[DIMM], g_sh2[DIMM];
#define WTOT 180224
__device__ unsigned g_wbh[WTOT];
__device__ unsigned g_wbl[WTOT];
__device__ int g_deg[NODES];       // zero-invariant
__device__ int g_off[NODES];
__device__ int g_pos[NODES];
__device__ int g_esrc[EMAX];
__device__ int g_bsum[256];
__device__ unsigned g_barcnt;      // zero-invariant grid-barrier counter

// ---------------- split helper ----------------
__device__ __forceinline__ void pack_split2(float x, float y, unsigned& h, unsigned& l) {
    __nv_bfloat16 xh = __float2bfloat16_rn(x);
    __nv_bfloat16 yh = __float2bfloat16_rn(y);
    __nv_bfloat16 xl = __float2bfloat16_rn(x - __bfloat162float(xh));
    __nv_bfloat16 yl = __float2bfloat16_rn(y - __bfloat162float(yh));
    h = (unsigned)(*(unsigned short*)&xh) | ((unsigned)(*(unsigned short*)&yh) << 16);
    l = (unsigned)(*(unsigned short*)&xl) | ((unsigned)(*(unsigned short*)&yl) << 16);
}

// ---------------- fused CSR build ----------------
#define CSRB 196

__device__ __forceinline__ void gridbar(int phase) {
    __syncthreads();
    if (threadIdx.x == 0) {
        __threadfence();
        atomicAdd(&g_barcnt, 1u);
        while (*((volatile unsigned*)&g_barcnt) < (unsigned)(phase * CSRB)) { }
        __threadfence();
    }
    __syncthreads();
}

__global__ __launch_bounds__(256)
void csr_build_kernel(const int* __restrict__ src, const int* __restrict__ dst, int E) {
    int b = blockIdx.x, t = threadIdx.x;
    int lane = t & 31, w = t >> 5;
    int gtid = b * 256 + t;
    int gstride = CSRB * 256;

    for (int i = gtid; i < E; i += gstride) atomicAdd(&g_deg[dst[i]], 1);
    gridbar(1);

    __shared__ int wsum[8];
    __shared__ int sm[256];
    int i0 = b * 512 + 2 * t;
    int d0 = (i0 < NODES) ? g_deg[i0] : 0;
    int d1 = (i0 + 1 < NODES) ? g_deg[i0 + 1] : 0;
    int pair = d0 + d1;
    int incl = pair;
    #pragma unroll
    for (int off = 1; off < 32; off <<= 1) {
        int v = __shfl_up_sync(0xffffffffu, incl, off);
        if (lane >= off) incl += v;
    }
    if (lane == 31) wsum[w] = incl;
    __syncthreads();
    if (w == 0 && lane < 8) {
        int v = wsum[lane];
        #pragma unroll
        for (int off = 1; off < 8; off <<= 1) {
            int u = __shfl_up_sync(0xffu, v, off);
            if (lane >= off) v += u;
        }
        wsum[lane] = v;
    }
    __syncthreads();
    int wbase = (w > 0) ? wsum[w - 1] : 0;
    int excl_local = wbase + incl - pair;
    if (t == 0) g_bsum[b] = wsum[7];
    gridbar(2);

    if (b == 0) {
        int orig = (t < CSRB) ? g_bsum[t] : 0;
        sm[t] = orig; __syncthreads();
        #pragma unroll
        for (int off = 1; off < 256; off <<= 1) {
            int v = (t >= off) ? sm[t - off] : 0;
            __syncthreads();
            sm[t] += v;
            __syncthreads();
        }
        if (t < CSRB) g_bsum[t] = sm[t] - orig;
    }
    gridbar(3);

    int base = g_bsum[b];
    int e0 = base + excl_local;
    if (i0 < NODES)     { g_off[i0] = e0;          g_pos[i0] = e0; }
    if (i0 + 1 < NODES) { g_off[i0 + 1] = e0 + d0; g_pos[i0 + 1] = e0 + d0; }
    gridbar(4);

    for (int i = gtid; i < E; i += gstride) {
        int d = dst[i];
        int p = atomicAdd(&g_pos[d], 1);
        g_esrc[p] = src[i];
    }
}

// ---------------- conv1 aggregate: fp32 gather from x + self -> packed pair (K=128) ----------------
__global__ __launch_bounds__(256)
void agg_f32_kernel(const float* __restrict__ x) {
    int w    = (blockIdx.x * blockDim.x + threadIdx.x) >> 5;
    int lane = threadIdx.x & 31;
    int nw   = (gridDim.x * blockDim.x) >> 5;
    const float4* xp = (const float4*)x + lane;
    for (int node = w; node < NODES; node += nw) {
        int beg = g_off[node];
        int cnt = g_deg[node];
        float4 a0 = __ldg(xp + (size_t)node * 32);   // self term
        float4 a1 = make_float4(0.f,0.f,0.f,0.f), a2 = a1, a3 = a1;
        for (int i0 = 0; i0 < cnt; i0 += 32) {
            int n = cnt - i0; if (n > 32) n = 32;
            int myidx = (i0 + lane < cnt) ? __ldg(&g_esrc[beg + i0 + lane]) : 0;
            int j = 0;
            for (; j + 4 <= n; j += 4) {
                int s0 = __shfl_sync(0xffffffffu, myidx, j);
                int s1 = __shfl_sync(0xffffffffu, myidx, j + 1);
                int s2 = __shfl_sync(0xffffffffu, myidx, j + 2);
                int s3 = __shfl_sync(0xffffffffu, myidx, j + 3);
                float4 v0 = __ldg(xp + (size_t)s0 * 32);
                float4 v1 = __ldg(xp + (size_t)s1 * 32);
                float4 v2 = __ldg(xp + (size_t)s2 * 32);
                float4 v3 = __ldg(xp + (size_t)s3 * 32);
                a0.x += v0.x; a0.y += v0.y; a0.z += v0.z; a0.w += v0.w;
                a1.x += v1.x; a1.y += v1.y; a1.z += v1.z; a1.w += v1.w;
                a2.x += v2.x; a2.y += v2.y; a2.z += v2.z; a2.w += v2.w;
                a3.x += v3.x; a3.y += v3.y; a3.z += v3.z; a3.w += v3.w;
            }
            for (; j < n; j++) {
                int s = __shfl_sync(0xffffffffu, myidx, j);
                float4 v = __ldg(xp + (size_t)s * 32);
                a0.x += v.x; a0.y += v.y; a0.z += v.z; a0.w += v.w;
            }
        }
        a0.x += a1.x + a2.x + a3.x;
        a0.y += a1.y + a2.y + a3.y;
        a0.z += a1.z + a2.z + a3.z;
        a0.w += a1.w + a2.w + a3.w;
        unsigned h0, l0, h1, l1;
        pack_split2(a0.x, a0.y, h0, l0);
        pack_split2(a0.z, a0.w, h1, l1);
        size_t o = (size_t)node * 64 + lane * 2;
        *(uint2*)&g_a0h[o] = make_uint2(h0, h1);
        *(uint2*)&g_a0l[o] = make_uint2(l0, l1);
    }
}

// ---------------- conv2/3 aggregate: fp16 raw-h gather + self, fused BN affine ----------------
// A = s ⊙ (h_self + Σ h_nbr) + (deg+1)·t, written as packed bf16 pair (K=256)
__device__ __forceinline__ void acc8(float* a, const uint4& v) {
    float2 f;
    f = __half22float2(*(__half2*)&v.x); a[0] += f.x; a[1] += f.y;
    f = __half22float2(*(__half2*)&v.y); a[2] += f.x; a[3] += f.y;
    f = __half22float2(*(__half2*)&v.z); a[4] += f.x; a[5] += f.y;
    f = __half22float2(*(__half2*)&v.w); a[6] += f.x; a[7] += f.y;
}

__global__ __launch_bounds__(256)
void agg_half_kernel(const __half* __restrict__ hh,
                     const float* __restrict__ sc, const float* __restrict__ sh) {
    int w    = (blockIdx.x * blockDim.x + threadIdx.x) >> 5;
    int lane = threadIdx.x & 31;
    int nw   = (gridDim.x * blockDim.x) >> 5;
    const uint4* hp = (const uint4*)hh + lane;
    float s[8], t[8];
    {
        const float4* scp = (const float4*)sc + lane * 2;
        const float4* shp = (const float4*)sh + lane * 2;
        *(float4*)&s[0] = __ldg(scp);
        *(float4*)&s[4] = __ldg(scp + 1);
        *(float4*)&t[0] = __ldg(shp);
        *(float4*)&t[4] = __ldg(shp + 1);
    }
    for (int node = w; node < NODES; node += nw) {
        int beg = g_off[node];
        int cnt = g_deg[node];
        float a[8] = {0.f,0.f,0.f,0.f,0.f,0.f,0.f,0.f};
        float b[8] = {0.f,0.f,0.f,0.f,0.f,0.f,0.f,0.f};
        uint4 self = __ldg(hp + (size_t)node * 32);
        acc8(a, self);
        for (int i0 = 0; i0 < cnt; i0 += 32) {
            int n = cnt - i0; if (n > 32) n = 32;
            int myidx = (i0 + lane < cnt) ? __ldg(&g_esrc[beg + i0 + lane]) : 0;
            int j = 0;
            for (; j + 4 <= n; j += 4) {
                int s0 = __shfl_sync(0xffffffffu, myidx, j);
                int s1 = __shfl_sync(0xffffffffu, myidx, j + 1);
                int s2 = __shfl_sync(0xffffffffu, myidx, j + 2);
                int s3 = __shfl_sync(0xffffffffu, myidx, j + 3);
                uint4 v0 = __ldg(hp + (size_t)s0 * 32);
                uint4 v1 = __ldg(hp + (size_t)s1 * 32);
                uint4 v2 = __ldg(hp + (size_t)s2 * 32);
                uint4 v3 = __ldg(hp + (size_t)s3 * 32);
                acc8(a, v0); acc8(b, v1); acc8(a, v2); acc8(b, v3);
            }
            for (; j < n; j++) {
                int s2 = __shfl_sync(0xffffffffu, myidx, j);
                uint4 v = __ldg(hp + (size_t)s2 * 32);
                acc8(a, v);
            }
        }
        float degp1 = (float)(cnt + 1);
        unsigned hw[4], lw[4];
        #pragma unroll
        for (int j = 0; j < 4; j++) {
            float v0 = fmaf(s[2*j],     a[2*j]     + b[2*j],     degp1 * t[2*j]);
            float v1 = fmaf(s[2*j + 1], a[2*j + 1] + b[2*j + 1], degp1 * t[2*j + 1]);
            pack_split2(v0, v1, hw[j], lw[j]);
        }
        size_t o = (size_t)node * 128 + lane * 4;
        *(uint4*)&g_a0h[o] = *(uint4*)hw;
        *(uint4*)&g_a0l[o] = *(uint4*)lw;
    }
}

// ---------------- weight pre-split into packed pair layout [k2][n] ----------------
__global__ void split_weights(const float* __restrict__ w1a, const float* __restrict__ w1b,
                              const float* __restrict__ w2a, const float* __restrict__ w2b,
                              const float* __restrict__ w3a, const float* __restrict__ w3b) {
    int i = blockIdx.x * blockDim.x + threadIdx.x;
    if (i >= WTOT) return;
    const float* w; int base;
    if      (i <  16384) { w = w1a; base = 0; }
    else if (i <  49152) { w = w1b; base = 16384; }
    else if (i <  81920) { w = w2a; base = 49152; }
    else if (i < 114688) { w = w2b; base = 81920; }
    else if (i < 147456) { w = w3a; base = 114688; }
    else                 { w = w3b; base = 147456; }
    int lw = i - base;
    int j2 = lw >> 8;
    int n  = lw & 255;
    float v0 = __ldg(&w[(size_t)(j2 * 2)     * 256 + n]);
    float v1 = __ldg(&w[(size_t)(j2 * 2 + 1) * 256 + n]);
    unsigned h, l;
    pack_split2(v0, v1, h, l);
    g_wbh[i] = h;
    g_wbl[i] = l;
}

// ---------------- bf16x3 GEMM on pre-split packed operands, 128x128 tile ----------------
// OMODE: 0 = packed bf16 pair out (Ch/Cl), 1 = fp16 out (Hh), 2 = fp32 out (Cf)
__device__ __forceinline__ void mma_bf16(float* c, const unsigned* a, const unsigned* b) {
    asm volatile(
        "mma.sync.aligned.m16n8k16.row.col.f32.bf16.bf16.f32 "
        "{%0,%1,%2,%3}, {%4,%5,%6,%7}, {%8,%9}, {%0,%1,%2,%3};"
        : "+f"(c[0]), "+f"(c[1]), "+f"(c[2]), "+f"(c[3])
        : "r"(a[0]), "r"(a[1]), "r"(a[2]), "r"(a[3]), "r"(b[0]), "r"(b[1]));
}

#define AW 12    // A smem row stride in words: conflict-free frag reads
#define BW 136   // B smem k2-row stride in words (128 data + 8 pad): conflict-free

template<int OMODE, bool STATS>
__global__ __launch_bounds__(256)
void gemm_pk_kernel(const unsigned* __restrict__ Ah, const unsigned* __restrict__ Al,
                    const unsigned* __restrict__ Bh, const unsigned* __restrict__ Bl,
                    const float* __restrict__ bias,
                    float* __restrict__ Cf, unsigned* __restrict__ Ch, unsigned* __restrict__ Cl,
                    unsigned* __restrict__ Hh,
                    float* __restrict__ sums, float* __restrict__ sqs,
                    int M, int K, int N) {
    __shared__ unsigned As_h[2][128 * AW];
    __shared__ unsigned As_l[2][128 * AW];
    __shared__ unsigned Bs_h[2][8 * BW];
    __shared__ unsigned Bs_l[2][8 * BW];

    const int tid  = threadIdx.x;
    const int lane = tid & 31;
    const int wid  = tid >> 5;
    const int wm   = wid & 3;
    const int wn   = wid >> 2;
    const int gid  = lane >> 2;
    const int tig  = lane & 3;
    const int row0 = blockIdx.x * 128;
    const int col0 = blockIdx.y * 128;
    const int K2   = K >> 1;

    float acc[2][8][4];
    #pragma unroll
    for (int mt = 0; mt < 2; mt++)
        #pragma unroll
        for (int nt = 0; nt < 8; nt++)
            #pragma unroll
            for (int i = 0; i < 4; i++) acc[mt][nt][i] = 0.f;

    const int ar  = tid >> 1;
    const int kw  = (tid & 1) * 4;
    const int agr = row0 + ar;
    const int bj  = tid >> 5;
    const int n4  = (tid & 31) * 4;

    uint4 avh, avl, bvh, bvl;

    auto load_tile = [&](int k0w) {
        if (agr < M) {
            avh = __ldg((const uint4*)(Ah + (size_t)agr * K2 + k0w + kw));
            avl = __ldg((const uint4*)(Al + (size_t)agr * K2 + k0w + kw));
        } else {
            avh = make_uint4(0,0,0,0);
            avl = make_uint4(0,0,0,0);
        }
        size_t bo = (size_t)(k0w + bj) * N + col0 + n4;
        bvh = __ldg((const uint4*)(Bh + bo));
        bvl = __ldg((const uint4*)(Bl + bo));
    };

    auto store_tile = [&](int p) {
        *(uint4*)&As_h[p][ar * AW + kw] = avh;
        *(uint4*)&As_l[p][ar * AW + kw] = avl;
        *(uint4*)&Bs_h[p][bj * BW + n4] = bvh;
        *(uint4*)&Bs_l[p][bj * BW + n4] = bvl;
    };

    load_tile(0);
    store_tile(0);
    __syncthreads();

    const int nT = K >> 4;
    for (int t = 0; t < nT; t++) {
        int p = t & 1;
        if (t + 1 < nT) load_tile((t + 1) << 3);

        unsigned ah[2][4], al[2][4], bh[8][2], bl[8][2];
        #pragma unroll
        for (int mt = 0; mt < 2; mt++) {
            int r = (wm * 32 + mt * 16 + gid) * AW;
            ah[mt][0] = As_h[p][r + tig];
            ah[mt][1] = As_h[p][r + 8 * AW + tig];
            ah[mt][2] = As_h[p][r + tig + 4];
            ah[mt][3] = As_h[p][r + 8 * AW + tig + 4];
            al[mt][0] = As_l[p][r + tig];
            al[mt][1] = As_l[p][r + 8 * AW + tig];
            al[mt][2] = As_l[p][r + tig + 4];
            al[mt][3] = As_l[p][r + 8 * AW + tig + 4];
        }
        #pragma unroll
        for (int nt = 0; nt < 8; nt++) {
            int c = wn * 64 + nt * 8 + gid;
            bh[nt][0] = Bs_h[p][tig * BW + c];
            bh[nt][1] = Bs_h[p][(tig + 4) * BW + c];
            bl[nt][0] = Bs_l[p][tig * BW + c];
            bl[nt][1] = Bs_l[p][(tig + 4) * BW + c];
        }
        #pragma unroll
        for (int mt = 0; mt < 2; mt++)
            #pragma unroll
            for (int nt = 0; nt < 8; nt++) {
                mma_bf16(acc[mt][nt], ah[mt], bh[nt]);
                mma_bf16(acc[mt][nt], ah[mt], bl[nt]);
                mma_bf16(acc[mt][nt], al[mt], bh[nt]);
            }

        if (t + 1 < nT) store_tile(1 - p);
        __syncthreads();
    }

    // ---- epilogue: bias + relu; write per OMODE; optional fused BN stats ----
    const int N2 = N >> 1;
    float cs0[8], cs1[8], cq0[8], cq1[8];
    if (STATS) {
        #pragma unroll
        for (int nt = 0; nt < 8; nt++) { cs0[nt]=0.f; cs1[nt]=0.f; cq0[nt]=0.f; cq1[nt]=0.f; }
    }
    #pragma unroll
    for (int mt = 0; mt < 2; mt++) {
        int gr0 = row0 + wm * 32 + mt * 16 + gid;
        #pragma unroll
        for (int nt = 0; nt < 8; nt++) {
            int cg = col0 + wn * 64 + nt * 8 + tig * 2;
            float b0 = __ldg(&bias[cg]);
            float b1 = __ldg(&bias[cg + 1]);
            float v0 = fmaxf(acc[mt][nt][0] + b0, 0.f);
            float v1 = fmaxf(acc[mt][nt][1] + b1, 0.f);
            float v2 = fmaxf(acc[mt][nt][2] + b0, 0.f);
            float v3 = fmaxf(acc[mt][nt][3] + b1, 0.f);
            int cg2 = cg >> 1;
            if (OMODE == 0) {
                unsigned h01, l01, h23, l23;
                pack_split2(v0, v1, h01, l01);
                pack_split2(v2, v3, h23, l23);
                if (gr0 < M)     { Ch[(size_t)gr0 * N2 + cg2] = h01; Cl[(size_t)gr0 * N2 + cg2] = l01; }
                if (gr0 + 8 < M) { Ch[(size_t)(gr0 + 8) * N2 + cg2] = h23; Cl[(size_t)(gr0 + 8) * N2 + cg2] = l23; }
            } else if (OMODE == 1) {
                __half2 p01 = __floats2half2_rn(v0, v1);
                __half2 p23 = __floats2half2_rn(v2, v3);
                if (gr0 < M)     Hh[(size_t)gr0 * N2 + cg2]       = *(unsigned*)&p01;
                if (gr0 + 8 < M) Hh[(size_t)(gr0 + 8) * N2 + cg2] = *(unsigned*)&p23;
            } else {
                if (gr0 < M)     *(float2*)(Cf + (size_t)gr0 * N + cg)       = make_float2(v0, v1);
                if (gr0 + 8 < M) *(float2*)(Cf + (size_t)(gr0 + 8) * N + cg) = make_float2(v2, v3);
            }
            if (STATS) {
                if (gr0 < M) {
                    cs0[nt] += v0; cs1[nt] += v1;
                    cq0[nt] = fmaf(v0, v0, cq0[nt]); cq1[nt] = fmaf(v1, v1, cq1[nt]);
                }
                if (gr0 + 8 < M) {
                    cs0[nt] += v2; cs1[nt] += v3;
                    cq0[nt] = fmaf(v2, v2, cq0[nt]); cq1[nt] = fmaf(v3, v3, cq1[nt]);
                }
            }
        }
    }
    if (STATS) {
        #pragma unroll
        for (int nt = 0; nt < 8; nt++) {
            #pragma unroll
            for (int off = 4; off < 32; off <<= 1) {
                cs0[nt] += __shfl_xor_sync(0xffffffffu, cs0[nt], off);
                cs1[nt] += __shfl_xor_sync(0xffffffffu, cs1[nt], off);
                cq0[nt] += __shfl_xor_sync(0xffffffffu, cq0[nt], off);
                cq1[nt] += __shfl_xor_sync(0xffffffffu, cq1[nt], off);
            }
            if (lane < 4) {
                int cg = col0 + wn * 64 + nt * 8 + lane * 2;
                atomicAdd(&sums[cg],     cs0[nt]);
                atomicAdd(&sums[cg + 1], cs1[nt]);
                atomicAdd(&sqs[cg],      cq0[nt]);
                atomicAdd(&sqs[cg + 1],  cq1[nt]);
            }
        }
    }
}

// ---------------- BN coefficient kernel: (sums,sqs,gamma,beta) -> (scale, shift) ----------------
__global__ void bn_coef_kernel(const float* __restrict__ sums, const float* __restrict__ sqs,
                               const float* __restrict__ gamma, const float* __restrict__ beta,
                               float* __restrict__ sc, float* __restrict__ sh, int M) {
    int c = threadIdx.x;
    float m   = sums[c] / (float)M;
    float v   = sqs[c] / (float)M - m * m;
    float s   = gamma[c] * rsqrtf(v + 1e-5f);
    sc[c] = s;
    sh[c] = beta[c] - m * s;
}

// ---------------- final fc (256->16) + log_softmax ----------------
__global__ void fc_lsm_kernel(const float* __restrict__ h, const float* __restrict__ wfc,
                              const float* __restrict__ bfc, float* __restrict__ out, int M) {
    __shared__ float ws[DIMM * 16];
    for (int i = threadIdx.x; i < DIMM * 16; i += blockDim.x) ws[i] = wfc[i];
    __syncthreads();

    int warp = threadIdx.x >> 5;
    int lane = threadIdx.x & 31;
    int c    = lane & 15;
    int half = lane >> 4;
    int row  = blockIdx.x * 8 + warp;
    if (row >= M) return;

    const float* hr = h + (size_t)row * DIMM;
    float acc = 0.f;
    int kbase = half * 128;
    #pragma unroll 8
    for (int k = 0; k < 128; k++)
        acc = fmaf(hr[kbase + k], ws[(kbase + k) * 16 + c], acc);
    acc += __shfl_xor_sync(0xffffffffu, acc, 16);

    float logit = acc + bfc[c];
    float m = logit;
    #pragma unroll
    for (int off = 8; off; off >>= 1)
        m = fmaxf(m, __shfl_xor_sync(0xffffffffu, m, off));
    float e = expf(logit - m);
    float s = e;
    #pragma unroll
    for (int off = 8; off; off >>= 1)
        s += __shfl_xor_sync(0xffffffffu, s, off);
    float r = logit - m - logf(s);
    if (lane < 16) out[(size_t)row * 16 + c] = r;
}

// ---------------- tail cleanup: restore zero-invariants ----------------
__global__ void cleanup_kernel() {
    int i = blockIdx.x * blockDim.x + threadIdx.x;
    if (i < NODES) g_deg[i] = 0;
    if (i < DIMM) { g_bns1[i] = 0.f; g_bnq1[i] = 0.f; g_bns2[i] = 0.f; g_bnq2[i] = 0.f; }
    if (i == 0) g_barcnt = 0u;
}

extern "C" void kernel_launch(void* const* d_in, const int* in_sizes, int n_in,
                              void* d_out, int out_size) {
    const float* x   = (const float*)d_in[0];
    const int*   ei  = (const int*)d_in[1];
    const float* w1a = (const float*)d_in[2];  const float* b1a = (const float*)d_in[3];
    const float* w1b = (const float*)d_in[4];  const float* b1b = (const float*)d_in[5];
    const float* g1  = (const float*)d_in[6];  const float* be1 = (const float*)d_in[7];
    const float* w2a = (const float*)d_in[8];  const float* b2a = (const float*)d_in[9];
    const float* w2b = (const float*)d_in[10]; const float* b2b = (const float*)d_in[11];
    const float* g2  = (const float*)d_in[12]; const float* be2 = (const float*)d_in[13];
    const float* w3a = (const float*)d_in[14]; const float* b3a = (const float*)d_in[15];
    const float* w3b = (const float*)d_in[16]; const float* b3b = (const float*)d_in[17];
    const float* wfc = (const float*)d_in[18]; const float* bfc = (const float*)d_in[19];
    float* out = (float*)d_out;

    const int M = NODES;
    const int E = in_sizes[1] / 2;
    const int* src = ei;
    const int* dst = ei + E;

    float *h, *bns1, *bnq1, *bns2, *bnq2, *sc1, *sh1, *sc2, *sh2;
    __half* hh;
    unsigned *a0h, *a0l, *zh, *zl, *wbh, *wbl, *hhu;
    cudaGetSymbolAddress((void**)&h,    g_h);
    cudaGetSymbolAddress((void**)&hh,   g_hhalf);
    cudaGetSymbolAddress((void**)&a0h,  g_a0h);
    cudaGetSymbolAddress((void**)&a0l,  g_a0l);
    cudaGetSymbolAddress((void**)&zh,   g_zh);
    cudaGetSymbolAddress((void**)&zl,   g_zl);
    cudaGetSymbolAddress((void**)&wbh,  g_wbh);
    cudaGetSymbolAddress((void**)&wbl,  g_wbl);
    cudaGetSymbolAddress((void**)&bns1, g_bns1);
    cudaGetSymbolAddress((void**)&bnq1, g_bnq1);
    cudaGetSymbolAddress((void**)&bns2, g_bns2);
    cudaGetSymbolAddress((void**)&bnq2, g_bnq2);
    cudaGetSymbolAddress((void**)&sc1,  g_sc1);
    cudaGetSymbolAddress((void**)&sh1,  g_sh1);
    cudaGetSymbolAddress((void**)&sc2,  g_sc2);
    cudaGetSymbolAddress((void**)&sh2,  g_sh2);
    hhu = (unsigned*)hh;

    dim3 ggrid((M + 127) / 128, 2);   // N=256 -> 2 col tiles of 128
    const int AGG_BLOCKS = 6250;

    // ---- launch 1: fused CSR build ----
    csr_build_kernel<<<CSRB, 256>>>(src, dst, E);

    // ---- conv1 ----
    agg_f32_kernel<<<AGG_BLOCKS, 256>>>(x);                                    // 2
    split_weights<<<(WTOT + 255) / 256, 256>>>(w1a, w1b, w2a, w2b, w3a, w3b);  // 3
    gemm_pk_kernel<0, false><<<ggrid, 256>>>(a0h, a0l, wbh, wbl, b1a,          // 4 = profiled
                                             nullptr, zh, zl, nullptr, nullptr, nullptr,
                                             M, 128, 256);
    gemm_pk_kernel<1, true ><<<ggrid, 256>>>(zh, zl, wbh + 16384, wbl + 16384, b1b,
                                             nullptr, nullptr, nullptr, hhu, bns1, bnq1,
                                             M, 256, 256);
    bn_coef_kernel<<<1, 256>>>(bns1, bnq1, g1, be1, sc1, sh1, M);

    // ---- conv2 ----
    agg_half_kernel<<<AGG_BLOCKS, 256>>>(hh, sc1, sh1);
    gemm_pk_kernel<0, false><<<ggrid, 256>>>(a0h, a0l, wbh + 49152, wbl + 49152, b2a,
                                             nullptr, zh, zl, nullptr, nullptr, nullptr,
                                             M, 256, 256);
    gemm_pk_kernel<1, true ><<<ggrid, 256>>>(zh, zl, wbh + 81920, wbl + 81920, b2b,
                                             nullptr, nullptr, nullptr, hhu, bns2, bnq2,
                                             M, 256, 256);
    bn_coef_kernel<<<1, 256>>>(bns2, bnq2, g2, be2, sc2, sh2, M);

    // ---- conv3 ----
    agg_half_kernel<<<AGG_BLOCKS, 256>>>(hh, sc2, sh2);
    gemm_pk_kernel<0, false><<<ggrid, 256>>>(a0h, a0l, wbh + 114688, wbl + 114688, b3a,
                                             nullptr, zh, zl, nullptr, nullptr, nullptr,
                                             M, 256, 256);
    gemm_pk_kernel<2, false><<<ggrid, 256>>>(zh, zl, wbh + 147456, wbl + 147456, b3b,
                                             h, nullptr, nullptr, nullptr, nullptr, nullptr,
                                             M, 256, 256);

    // ---- fc + log_softmax ----
    fc_lsm_kernel<<<(M + 7) / 8, 256>>>(h, wfc, bfc, out, M);

    // ---- restore zero-invariants ----
    cleanup_kernel<<<(NODES + 255) / 256, 256>>>();
}

// round 16
// speedup vs baseline: 1.1485x; 1.1485x over previous
#include <cuda_runtime.h>
#include <cuda_fp16.h>
#include <math.h>

#define NODES 100000
#define EMAX  3200000
#define DIMM  256

// ---------------- scratch (device globals; no allocation allowed) ----------------
// Packed fp16 pairs: word = fp16(k even) | fp16(k odd)<<16, layout [row][K/2]
__device__ unsigned g_a0h[(size_t)NODES * 128];   // A high
__device__ unsigned g_a0l[(size_t)NODES * 128];   // A residual
__device__ unsigned g_zh [(size_t)NODES * 128];
__device__ unsigned g_zl [(size_t)NODES * 128];
__device__ float  g_h[(size_t)NODES * DIMM];
__device__ __half g_hhalf[(size_t)NODES * DIMM];
__device__ float g_bns1[DIMM], g_bnq1[DIMM];   // zero-invariant (cleanup kernel)
__device__ float g_bns2[DIMM], g_bnq2[DIMM];
#define WTOT 180224
__device__ unsigned g_wfh[WTOT];   // weights packed fp16 pairs, [k2][n]
__device__ int g_deg[NODES];       // zero-invariant
__device__ int g_off[NODES];
__device__ int g_pos[NODES];
__device__ int g_esrc[EMAX];
__device__ int g_bsum[256];
__device__ unsigned g_barcnt;      // zero-invariant grid-barrier counter

// ---------------- fp16 split helper ----------------
__device__ __forceinline__ void pack_split2(float x, float y, unsigned& h, unsigned& l) {
    __half xh = __float2half_rn(x);
    __half yh = __float2half_rn(y);
    __half xl = __float2half_rn(x - __half2float(xh));
    __half yl = __float2half_rn(y - __half2float(yh));
    h = (unsigned)(*(unsigned short*)&xh) | ((unsigned)(*(unsigned short*)&yh) << 16);
    l = (unsigned)(*(unsigned short*)&xl) | ((unsigned)(*(unsigned short*)&yl) << 16);
}
__device__ __forceinline__ unsigned pack_f16(float x, float y) {
    __half2 p = __floats2half2_rn(x, y);
    return *(unsigned*)&p;
}

// ---------------- fused CSR build ----------------
#define CSRB 196

__device__ __forceinline__ void gridbar(int phase) {
    __syncthreads();
    if (threadIdx.x == 0) {
        __threadfence();
        atomicAdd(&g_barcnt, 1u);
        while (*((volatile unsigned*)&g_barcnt) < (unsigned)(phase * CSRB)) { }
        __threadfence();
    }
    __syncthreads();
}

__global__ __launch_bounds__(256)
void csr_build_kernel(const int* __restrict__ src, const int* __restrict__ dst, int E) {
    int b = blockIdx.x, t = threadIdx.x;
    int lane = t & 31, w = t >> 5;
    int gtid = b * 256 + t;
    int gstride = CSRB * 256;

    for (int i = gtid; i < E; i += gstride) atomicAdd(&g_deg[dst[i]], 1);
    gridbar(1);

    __shared__ int wsum[8];
    __shared__ int sm[256];
    int i0 = b * 512 + 2 * t;
    int d0 = (i0 < NODES) ? g_deg[i0] : 0;
    int d1 = (i0 + 1 < NODES) ? g_deg[i0 + 1] : 0;
    int pair = d0 + d1;
    int incl = pair;
    #pragma unroll
    for (int off = 1; off < 32; off <<= 1) {
        int v = __shfl_up_sync(0xffffffffu, incl, off);
        if (lane >= off) incl += v;
    }
    if (lane == 31) wsum[w] = incl;
    __syncthreads();
    if (w == 0 && lane < 8) {
        int v = wsum[lane];
        #pragma unroll
        for (int off = 1; off < 8; off <<= 1) {
            int u = __shfl_up_sync(0xffu, v, off);
            if (lane >= off) v += u;
        }
        wsum[lane] = v;
    }
    __syncthreads();
    int wbase = (w > 0) ? wsum[w - 1] : 0;
    int excl_local = wbase + incl - pair;
    if (t == 0) g_bsum[b] = wsum[7];
    gridbar(2);

    if (b == 0) {
        int orig = (t < CSRB) ? g_bsum[t] : 0;
        sm[t] = orig; __syncthreads();
        #pragma unroll
        for (int off = 1; off < 256; off <<= 1) {
            int v = (t >= off) ? sm[t - off] : 0;
            __syncthreads();
            sm[t] += v;
            __syncthreads();
        }
        if (t < CSRB) g_bsum[t] = sm[t] - orig;
    }
    gridbar(3);

    int base = g_bsum[b];
    int e0 = base + excl_local;
    if (i0 < NODES)     { g_off[i0] = e0;          g_pos[i0] = e0; }
    if (i0 + 1 < NODES) { g_off[i0 + 1] = e0 + d0; g_pos[i0 + 1] = e0 + d0; }
    gridbar(4);

    for (int i = gtid; i < E; i += gstride) {
        int d = dst[i];
        int p = atomicAdd(&g_pos[d], 1);
        g_esrc[p] = src[i];
    }
}

// ---------------- conv1 aggregate: fp32 gather from x + self -> packed fp16 pair (K=128) ----------------
__global__ __launch_bounds__(256)
void agg_f32_kernel(const float* __restrict__ x) {
    int w    = (blockIdx.x * blockDim.x + threadIdx.x) >> 5;
    int lane = threadIdx.x & 31;
    int nw   = (gridDim.x * blockDim.x) >> 5;
    const float4* xp = (const float4*)x + lane;
    for (int node = w; node < NODES; node += nw) {
        int beg = g_off[node];
        int cnt = g_deg[node];
        float4 a0 = __ldg(xp + (size_t)node * 32);   // self term
        float4 a1 = make_float4(0.f,0.f,0.f,0.f), a2 = a1, a3 = a1;
        for (int i0 = 0; i0 < cnt; i0 += 32) {
            int n = cnt - i0; if (n > 32) n = 32;
            int myidx = (i0 + lane < cnt) ? __ldg(&g_esrc[beg + i0 + lane]) : 0;
            int j = 0;
            for (; j + 4 <= n; j += 4) {
                int s0 = __shfl_sync(0xffffffffu, myidx, j);
                int s1 = __shfl_sync(0xffffffffu, myidx, j + 1);
                int s2 = __shfl_sync(0xffffffffu, myidx, j + 2);
                int s3 = __shfl_sync(0xffffffffu, myidx, j + 3);
                float4 v0 = __ldg(xp + (size_t)s0 * 32);
                float4 v1 = __ldg(xp + (size_t)s1 * 32);
                float4 v2 = __ldg(xp + (size_t)s2 * 32);
                float4 v3 = __ldg(xp + (size_t)s3 * 32);
                a0.x += v0.x; a0.y += v0.y; a0.z += v0.z; a0.w += v0.w;
                a1.x += v1.x; a1.y += v1.y; a1.z += v1.z; a1.w += v1.w;
                a2.x += v2.x; a2.y += v2.y; a2.z += v2.z; a2.w += v2.w;
                a3.x += v3.x; a3.y += v3.y; a3.z += v3.z; a3.w += v3.w;
            }
            for (; j < n; j++) {
                int s = __shfl_sync(0xffffffffu, myidx, j);
                float4 v = __ldg(xp + (size_t)s * 32);
                a0.x += v.x; a0.y += v.y; a0.z += v.z; a0.w += v.w;
            }
        }
        a0.x += a1.x + a2.x + a3.x;
        a0.y += a1.y + a2.y + a3.y;
        a0.z += a1.z + a2.z + a3.z;
        a0.w += a1.w + a2.w + a3.w;
        unsigned h0, l0, h1, l1;
        pack_split2(a0.x, a0.y, h0, l0);
        pack_split2(a0.z, a0.w, h1, l1);
        size_t o = (size_t)node * 64 + lane * 2;
        *(uint2*)&g_a0h[o] = make_uint2(h0, h1);
        *(uint2*)&g_a0l[o] = make_uint2(l0, l1);
    }
}

// ---------------- conv2/3 aggregate: fp16 gather + self -> packed fp16 pair (K=256) ----------------
__device__ __forceinline__ void acc8(float* a, const uint4& v) {
    float2 f;
    f = __half22float2(*(__half2*)&v.x); a[0] += f.x; a[1] += f.y;
    f = __half22float2(*(__half2*)&v.y); a[2] += f.x; a[3] += f.y;
    f = __half22float2(*(__half2*)&v.z); a[4] += f.x; a[5] += f.y;
    f = __half22float2(*(__half2*)&v.w); a[6] += f.x; a[7] += f.y;
}

__global__ __launch_bounds__(256)
void agg_half_kernel(const __half* __restrict__ hh) {
    int w    = (blockIdx.x * blockDim.x + threadIdx.x) >> 5;
    int lane = threadIdx.x & 31;
    int nw   = (gridDim.x * blockDim.x) >> 5;
    const uint4* hp = (const uint4*)hh + lane;
    for (int node = w; node < NODES; node += nw) {
        int beg = g_off[node];
        int cnt = g_deg[node];
        float a[8] = {0.f,0.f,0.f,0.f,0.f,0.f,0.f,0.f};
        float b[8] = {0.f,0.f,0.f,0.f,0.f,0.f,0.f,0.f};
        uint4 self = __ldg(hp + (size_t)node * 32);
        acc8(a, self);
        for (int i0 = 0; i0 < cnt; i0 += 32) {
            int n = cnt - i0; if (n > 32) n = 32;
            int myidx = (i0 + lane < cnt) ? __ldg(&g_esrc[beg + i0 + lane]) : 0;
            int j = 0;
            for (; j + 4 <= n; j += 4) {
                int s0 = __shfl_sync(0xffffffffu, myidx, j);
                int s1 = __shfl_sync(0xffffffffu, myidx, j + 1);
                int s2 = __shfl_sync(0xffffffffu, myidx, j + 2);
                int s3 = __shfl_sync(0xffffffffu, myidx, j + 3);
                uint4 v0 = __ldg(hp + (size_t)s0 * 32);
                uint4 v1 = __ldg(hp + (size_t)s1 * 32);
                uint4 v2 = __ldg(hp + (size_t)s2 * 32);
                uint4 v3 = __ldg(hp + (size_t)s3 * 32);
                acc8(a, v0); acc8(b, v1); acc8(a, v2); acc8(b, v3);
            }
            for (; j < n; j++) {
                int s = __shfl_sync(0xffffffffu, myidx, j);
                uint4 v = __ldg(hp + (size_t)s * 32);
                acc8(a, v);
            }
        }
        unsigned hw[4], lw[4];
        #pragma unroll
        for (int j = 0; j < 4; j++)
            pack_split2(a[2*j] + b[2*j], a[2*j+1] + b[2*j+1], hw[j], lw[j]);
        size_t o = (size_t)node * 128 + lane * 4;
        *(uint4*)&g_a0h[o] = *(uint4*)hw;
        *(uint4*)&g_a0l[o] = *(uint4*)lw;
    }
}

// ---------------- weight pre-split: single fp16 packed pairs, [k2][n] ----------------
__global__ void split_weights(const float* __restrict__ w1a, const float* __restrict__ w1b,
                              const float* __restrict__ w2a, const float* __restrict__ w2b,
                              const float* __restrict__ w3a, const float* __restrict__ w3b) {
    int i = blockIdx.x * blockDim.x + threadIdx.x;
    if (i >= WTOT) return;
    const float* w; int base;
    if      (i <  16384) { w = w1a; base = 0; }
    else if (i <  49152) { w = w1b; base = 16384; }
    else if (i <  81920) { w = w2a; base = 49152; }
    else if (i < 114688) { w = w2b; base = 81920; }
    else if (i < 147456) { w = w3a; base = 114688; }
    else                 { w = w3b; base = 147456; }
    int lw = i - base;
    int j2 = lw >> 8;
    int n  = lw & 255;
    float v0 = __ldg(&w[(size_t)(j2 * 2)     * 256 + n]);
    float v1 = __ldg(&w[(size_t)(j2 * 2 + 1) * 256 + n]);
    g_wfh[i] = pack_f16(v0, v1);
}

// ---------------- fp16 2-term GEMM (A = ah+al split, B single fp16), 128x128 tile ----------------
// C = relu(A@B + bias). WRITE_PAIR: packed fp16 split pair out; else fp32. STATS: fused BN sums.
__device__ __forceinline__ void mma_f16(float* c, const unsigned* a, const unsigned* b) {
    asm volatile(
        "mma.sync.aligned.m16n8k16.row.col.f32.f16.f16.f32 "
        "{%0,%1,%2,%3}, {%4,%5,%6,%7}, {%8,%9}, {%0,%1,%2,%3};"
        : "+f"(c[0]), "+f"(c[1]), "+f"(c[2]), "+f"(c[3])
        : "r"(a[0]), "r"(a[1]), "r"(a[2]), "r"(a[3]), "r"(b[0]), "r"(b[1]));
}

#define AW 12    // A smem row stride in words: conflict-free frag reads
#define BW 136   // B smem k2-row stride in words (128 data + 8 pad): conflict-free

template<bool WRITE_PAIR, bool STATS>
__global__ __launch_bounds__(256)
void gemm_pk_kernel(const unsigned* __restrict__ Ah, const unsigned* __restrict__ Al,
                    const unsigned* __restrict__ Bh,
                    const float* __restrict__ bias,
                    float* __restrict__ Cf, unsigned* __restrict__ Ch, unsigned* __restrict__ Cl,
                    float* __restrict__ sums, float* __restrict__ sqs,
                    int M, int K, int N) {
    __shared__ unsigned As_h[2][128 * AW];
    __shared__ unsigned As_l[2][128 * AW];
    __shared__ unsigned Bs_h[2][8 * BW];

    const int tid  = threadIdx.x;
    const int lane = tid & 31;
    const int wid  = tid >> 5;
    const int wm   = wid & 3;
    const int wn   = wid >> 2;
    const int gid  = lane >> 2;
    const int tig  = lane & 3;
    const int row0 = blockIdx.x * 128;
    const int col0 = blockIdx.y * 128;
    const int K2   = K >> 1;

    float acc[2][8][4];
    #pragma unroll
    for (int mt = 0; mt < 2; mt++)
        #pragma unroll
        for (int nt = 0; nt < 8; nt++)
            #pragma unroll
            for (int i = 0; i < 4; i++) acc[mt][nt][i] = 0.f;

    const int ar  = tid >> 1;
    const int kw  = (tid & 1) * 4;
    const int agr = row0 + ar;
    const int bj  = tid >> 5;
    const int n4  = (tid & 31) * 4;

    uint4 avh, avl, bvh;

    auto load_tile = [&](int k0w) {
        if (agr < M) {
            avh = __ldg((const uint4*)(Ah + (size_t)agr * K2 + k0w + kw));
            avl = __ldg((const uint4*)(Al + (size_t)agr * K2 + k0w + kw));
        } else {
            avh = make_uint4(0,0,0,0);
            avl = make_uint4(0,0,0,0);
        }
        bvh = __ldg((const uint4*)(Bh + (size_t)(k0w + bj) * N + col0 + n4));
    };

    auto store_tile = [&](int p) {
        *(uint4*)&As_h[p][ar * AW + kw] = avh;
        *(uint4*)&As_l[p][ar * AW + kw] = avl;
        *(uint4*)&Bs_h[p][bj * BW + n4] = bvh;
    };

    load_tile(0);
    store_tile(0);
    __syncthreads();

    const int nT = K >> 4;
    for (int t = 0; t < nT; t++) {
        int p = t & 1;
        if (t + 1 < nT) load_tile((t + 1) << 3);

        unsigned ah[2][4], al[2][4], bh[8][2];
        #pragma unroll
        for (int mt = 0; mt < 2; mt++) {
            int r = (wm * 32 + mt * 16 + gid) * AW;
            ah[mt][0] = As_h[p][r + tig];
            ah[mt][1] = As_h[p][r + 8 * AW + tig];
            ah[mt][2] = As_h[p][r + tig + 4];
            ah[mt][3] = As_h[p][r + 8 * AW + tig + 4];
            al[mt][0] = As_l[p][r + tig];
            al[mt][1] = As_l[p][r + 8 * AW + tig];
            al[mt][2] = As_l[p][r + tig + 4];
            al[mt][3] = As_l[p][r + 8 * AW + tig + 4];
        }
        #pragma unroll
        for (int nt = 0; nt < 8; nt++) {
            int c = wn * 64 + nt * 8 + gid;
            bh[nt][0] = Bs_h[p][tig * BW + c];
            bh[nt][1] = Bs_h[p][(tig + 4) * BW + c];
        }
        #pragma unroll
        for (int mt = 0; mt < 2; mt++)
            #pragma unroll
            for (int nt = 0; nt < 8; nt++) {
                mma_f16(acc[mt][nt], ah[mt], bh[nt]);
                mma_f16(acc[mt][nt], al[mt], bh[nt]);
            }

        if (t + 1 < nT) store_tile(1 - p);
        __syncthreads();
    }

    // ---- epilogue: bias + relu; write; optional fused BN stats ----
    const int N2 = N >> 1;
    float cs0[8], cs1[8], cq0[8], cq1[8];
    if (STATS) {
        #pragma unroll
        for (int nt = 0; nt < 8; nt++) { cs0[nt]=0.f; cs1[nt]=0.f; cq0[nt]=0.f; cq1[nt]=0.f; }
    }
    #pragma unroll
    for (int mt = 0; mt < 2; mt++) {
        int gr0 = row0 + wm * 32 + mt * 16 + gid;
        #pragma unroll
        for (int nt = 0; nt < 8; nt++) {
            int cg = col0 + wn * 64 + nt * 8 + tig * 2;
            float b0 = __ldg(&bias[cg]);
            float b1 = __ldg(&bias[cg + 1]);
            float v0 = fmaxf(acc[mt][nt][0] + b0, 0.f);
            float v1 = fmaxf(acc[mt][nt][1] + b1, 0.f);
            float v2 = fmaxf(acc[mt][nt][2] + b0, 0.f);
            float v3 = fmaxf(acc[mt][nt][3] + b1, 0.f);
            if (WRITE_PAIR) {
                unsigned h01, l01, h23, l23;
                pack_split2(v0, v1, h01, l01);
                pack_split2(v2, v3, h23, l23);
                int cg2 = cg >> 1;
                if (gr0 < M)     { Ch[(size_t)gr0 * N2 + cg2] = h01; Cl[(size_t)gr0 * N2 + cg2] = l01; }
                if (gr0 + 8 < M) { Ch[(size_t)(gr0 + 8) * N2 + cg2] = h23; Cl[(size_t)(gr0 + 8) * N2 + cg2] = l23; }
            } else {
                if (gr0 < M)     *(float2*)(Cf + (size_t)gr0 * N + cg)       = make_float2(v0, v1);
                if (gr0 + 8 < M) *(float2*)(Cf + (size_t)(gr0 + 8) * N + cg) = make_float2(v2, v3);
            }
            if (STATS) {
                if (gr0 < M) {
                    cs0[nt] += v0; cs1[nt] += v1;
                    cq0[nt] = fmaf(v0, v0, cq0[nt]); cq1[nt] = fmaf(v1, v1, cq1[nt]);
                }
                if (gr0 + 8 < M) {
                    cs0[nt] += v2; cs1[nt] += v3;
                    cq0[nt] = fmaf(v2, v2, cq0[nt]); cq1[nt] = fmaf(v3, v3, cq1[nt]);
                }
            }
        }
    }
    if (STATS) {
        #pragma unroll
        for (int nt = 0; nt < 8; nt++) {
            #pragma unroll
            for (int off = 4; off < 32; off <<= 1) {
                cs0[nt] += __shfl_xor_sync(0xffffffffu, cs0[nt], off);
                cs1[nt] += __shfl_xor_sync(0xffffffffu, cs1[nt], off);
                cq0[nt] += __shfl_xor_sync(0xffffffffu, cq0[nt], off);
                cq1[nt] += __shfl_xor_sync(0xffffffffu, cq1[nt], off);
            }
            if (lane < 4) {
                int cg = col0 + wn * 64 + nt * 8 + lane * 2;
                atomicAdd(&sums[cg],     cs0[nt]);
                atomicAdd(&sums[cg + 1], cs1[nt]);
                atomicAdd(&sqs[cg],      cq0[nt]);
                atomicAdd(&sqs[cg + 1],  cq1[nt]);
            }
        }
    }
}

// ---------------- batchnorm apply (in place) + fp16 copy ----------------
__global__ void bn_apply_kernel(float* __restrict__ h, __half* __restrict__ hh,
                                const float* __restrict__ gamma, const float* __restrict__ beta,
                                const float* __restrict__ sums, const float* __restrict__ sqs,
                                int M) {
    __shared__ float sc[DIMM], sh[DIMM];
    int t = threadIdx.x;
    if (t < DIMM) {
        float m   = sums[t] / (float)M;
        float v   = sqs[t] / (float)M - m * m;
        float inv = rsqrtf(v + 1e-5f);
        float s   = gamma[t] * inv;
        sc[t] = s;
        sh[t] = beta[t] - m * s;
    }
    __syncthreads();
    size_t n4 = (size_t)M * DIMM / 4;
    float4* h4 = (float4*)h;
    uint2*  hh4 = (uint2*)hh;
    for (size_t i = (size_t)blockIdx.x * blockDim.x + t; i < n4;
         i += (size_t)gridDim.x * blockDim.x) {
        int cb = (int)((i * 4) & (DIMM - 1));
        float4 v = h4[i];
        v.x = fmaf(v.x, sc[cb + 0], sh[cb + 0]);
        v.y = fmaf(v.y, sc[cb + 1], sh[cb + 1]);
        v.z = fmaf(v.z, sc[cb + 2], sh[cb + 2]);
        v.w = fmaf(v.w, sc[cb + 3], sh[cb + 3]);
        h4[i] = v;
        __half2 p0 = __floats2half2_rn(v.x, v.y);
        __half2 p1 = __floats2half2_rn(v.z, v.w);
        hh4[i] = make_uint2(*(unsigned*)&p0, *(unsigned*)&p1);
    }
}

// ---------------- final fc (256->16) + log_softmax ----------------
__global__ void fc_lsm_kernel(const float* __restrict__ h, const float* __restrict__ wfc,
                              const float* __restrict__ bfc, float* __restrict__ out, int M) {
    __shared__ float ws[DIMM * 16];
    for (int i = threadIdx.x; i < DIMM * 16; i += blockDim.x) ws[i] = wfc[i];
    __syncthreads();

    int warp = threadIdx.x >> 5;
    int lane = threadIdx.x & 31;
    int c    = lane & 15;
    int half = lane >> 4;
    int row  = blockIdx.x * 8 + warp;
    if (row >= M) return;

    const float* hr = h + (size_t)row * DIMM;
    float acc = 0.f;
    int kbase = half * 128;
    #pragma unroll 8
    for (int k = 0; k < 128; k++)
        acc = fmaf(hr[kbase + k], ws[(kbase + k) * 16 + c], acc);
    acc += __shfl_xor_sync(0xffffffffu, acc, 16);

    float logit = acc + bfc[c];
    float m = logit;
    #pragma unroll
    for (int off = 8; off; off >>= 1)
        m = fmaxf(m, __shfl_xor_sync(0xffffffffu, m, off));
    float e = expf(logit - m);
    float s = e;
    #pragma unroll
    for (int off = 8; off; off >>= 1)
        s += __shfl_xor_sync(0xffffffffu, s, off);
    float r = logit - m - logf(s);
    if (lane < 16) out[(size_t)row * 16 + c] = r;
}

// ---------------- tail cleanup: restore zero-invariants ----------------
__global__ void cleanup_kernel() {
    int i = blockIdx.x * blockDim.x + threadIdx.x;
    if (i < NODES) g_deg[i] = 0;
    if (i < DIMM) { g_bns1[i] = 0.f; g_bnq1[i] = 0.f; g_bns2[i] = 0.f; g_bnq2[i] = 0.f; }
    if (i == 0) g_barcnt = 0u;
}

extern "C" void kernel_launch(void* const* d_in, const int* in_sizes, int n_in,
                              void* d_out, int out_size) {
    const float* x   = (const float*)d_in[0];
    const int*   ei  = (const int*)d_in[1];
    const float* w1a = (const float*)d_in[2];  const float* b1a = (const float*)d_in[3];
    const float* w1b = (const float*)d_in[4];  const float* b1b = (const float*)d_in[5];
    const float* g1  = (const float*)d_in[6];  const float* be1 = (const float*)d_in[7];
    const float* w2a = (const float*)d_in[8];  const float* b2a = (const float*)d_in[9];
    const float* w2b = (const float*)d_in[10]; const float* b2b = (const float*)d_in[11];
    const float* g2  = (const float*)d_in[12]; const float* be2 = (const float*)d_in[13];
    const float* w3a = (const float*)d_in[14]; const float* b3a = (const float*)d_in[15];
    const float* w3b = (const float*)d_in[16]; const float* b3b = (const float*)d_in[17];
    const float* wfc = (const float*)d_in[18]; const float* bfc = (const float*)d_in[19];
    float* out = (float*)d_out;

    const int M = NODES;
    const int E = in_sizes[1] / 2;
    const int* src = ei;
    const int* dst = ei + E;

    float *h, *bns1, *bnq1, *bns2, *bnq2;
    __half* hh;
    unsigned *a0h, *a0l, *zh, *zl, *wfh;
    cudaGetSymbolAddress((void**)&h,    g_h);
    cudaGetSymbolAddress((void**)&hh,   g_hhalf);
    cudaGetSymbolAddress((void**)&a0h,  g_a0h);
    cudaGetSymbolAddress((void**)&a0l,  g_a0l);
    cudaGetSymbolAddress((void**)&zh,   g_zh);
    cudaGetSymbolAddress((void**)&zl,   g_zl);
    cudaGetSymbolAddress((void**)&wfh,  g_wfh);
    cudaGetSymbolAddress((void**)&bns1, g_bns1);
    cudaGetSymbolAddress((void**)&bnq1, g_bnq1);
    cudaGetSymbolAddress((void**)&bns2, g_bns2);
    cudaGetSymbolAddress((void**)&bnq2, g_bnq2);

    dim3 ggrid((M + 127) / 128, 2);   // N=256 -> 2 col tiles of 128
    const int AGG_BLOCKS = 6250;

    // ---- launch 1: fused CSR build ----
    csr_build_kernel<<<CSRB, 256>>>(src, dst, E);

    // ---- conv1 ----
    agg_f32_kernel<<<AGG_BLOCKS, 256>>>(x);                                    // 2
    split_weights<<<(WTOT + 255) / 256, 256>>>(w1a, w1b, w2a, w2b, w3a, w3b);  // 3
    gemm_pk_kernel<true,  false><<<ggrid, 256>>>(a0h, a0l, wfh, b1a,           // 4 = profiled
                                                 nullptr, zh, zl, nullptr, nullptr, M, 128, 256);
    gemm_pk_kernel<false, true ><<<ggrid, 256>>>(zh, zl, wfh + 16384, b1b,
                                                 h, nullptr, nullptr, bns1, bnq1, M, 256, 256);
    bn_apply_kernel<<<4096, 256>>>(h, hh, g1, be1, bns1, bnq1, M);

    // ---- conv2 ----
    agg_half_kernel<<<AGG_BLOCKS, 256>>>(hh);
    gemm_pk_kernel<true,  false><<<ggrid, 256>>>(a0h, a0l, wfh + 49152, b2a,
                                                 nullptr, zh, zl, nullptr, nullptr, M, 256, 256);
    gemm_pk_kernel<false, true ><<<ggrid, 256>>>(zh, zl, wfh + 81920, b2b,
                                                 h, nullptr, nullptr, bns2, bnq2, M, 256, 256);
    bn_apply_kernel<<<4096, 256>>>(h, hh, g2, be2, bns2, bnq2, M);

    // ---- conv3 ----
    agg_half_kernel<<<AGG_BLOCKS, 256>>>(hh);
    gemm_pk_kernel<true,  false><<<ggrid, 256>>>(a0h, a0l, wfh + 114688, b3a,
                                                 nullptr, zh, zl, nullptr, nullptr, M, 256, 256);
    gemm_pk_kernel<false, false><<<ggrid, 256>>>(zh, zl, wfh + 147456, b3b,
                                                 h, nullptr, nullptr, nullptr, nullptr, M, 256, 256);

    // ---- fc + log_softmax ----
    fc_lsm_kernel<<<(M + 7) / 8, 256>>>(h, wfc, bfc, out, M);

    // ---- restore zero-invariants ----
    cleanup_kernel<<<(NODES + 255) / 256, 256>>>();
}